// round 9
// baseline (speedup 1.0000x reference)
#include <cuda_runtime.h>
#include <cstdint>

// Problem constants
#define HOP     128
#define WINL    512
#define PADW    192
#define NB      32
#define NT      131072
#define NFRM    1024
#define NSTAGE  11

// Tiling: 32 threads/block, 2 frames per lane (lane-lo f, lane-hi f+32)
#define NFB     32
#define FPB     64                         // frames per block
#define BLK_PER_B (NFRM / FPB)             // 16
#define SPAN    ((FPB - 1) * HOP + WINL)   // 8576
#define NROWS   (SPAN / HOP)               // 67
#define SMEMN   (NROWS * (HOP + 1))        // 8643 floats (129-word rows)
#define SMEM_BYTES ((SMEMN + WINL) * sizeof(float))   // 36620 B -> 6 blocks/SM, single wave

#define TWO_PI_OVER_WIN 0.012271846303085129f

typedef unsigned long long u64;

// ---- packed f32x2 primitives ----
#define PK2(D, LO, HI) \
    asm("mov.b64 %0, {%1, %2};" : "=l"(D) : "r"(__float_as_uint(LO)), "r"(__float_as_uint(HI)))
#define UP2(FL, FH, S) { unsigned _ua, _ub;                                        \
    asm("mov.b64 {%0, %1}, %2;" : "=r"(_ua), "=r"(_ub) : "l"(S));                  \
    (FL) = __uint_as_float(_ua); (FH) = __uint_as_float(_ub); }
#define FMA2(D, A, B, C) \
    asm("fma.rn.f32x2 %0, %1, %2, %3;" : "=l"(D) : "l"(A), "l"(B), "l"(C))
#define MUL2(D, A, B) \
    asm("mul.rn.f32x2 %0, %1, %2;" : "=l"(D) : "l"(A), "l"(B))

__device__ __forceinline__ int pidx(int i) { return i + (i >> 7); }

__device__ __forceinline__ float hannw(int n) {
    return 0.5f - 0.5f * __cosf((float)n * TWO_PI_OVER_WIN);
}

__device__ float norm_at(int p) {
    int f_hi = p >> 7; if (f_hi > NFRM - 1) f_hi = NFRM - 1;
    int f_lo = (p >= 384) ? ((p - 384) >> 7) : 0;
    float s = 0.f;
    for (int f = f_lo; f <= f_hi; ++f) s += hannw(p - (f << 7));
    return s;
}

__global__ void halo_zero_kernel(float* __restrict__ out) {
    int b   = blockIdx.y;
    int blk = blockIdx.x + 1;
    int u   = blk * (FPB * HOP) - PADW + (int)threadIdx.x;
    out[(size_t)b * NT + u] = 0.f;
}

// Frame-packed cascade step: both lanes run the scalar recurrence
//   D[s] = na2[s]*D[s] + (na1[s]*S[s] + in(s)), in(0)=X, in(s)=S[s-1]
// for two independent frames. Feed pairs are whole u64s -> zero repack movs.
#define CAS2(S, D, X) {                                               \
    u64 _i0,_i1,_i2,_i3,_i4,_i5,_i6,_i7,_i8,_i9,_i10;                 \
    FMA2(_i0,  A1_0,  S##0,  (X));                                    \
    FMA2(_i1,  A1_1,  S##1,  S##0);                                   \
    FMA2(_i2,  A1_2,  S##2,  S##1);                                   \
    FMA2(_i3,  A1_3,  S##3,  S##2);                                   \
    FMA2(_i4,  A1_4,  S##4,  S##3);                                   \
    FMA2(_i5,  A1_5,  S##5,  S##4);                                   \
    FMA2(_i6,  A1_6,  S##6,  S##5);                                   \
    FMA2(_i7,  A1_7,  S##7,  S##6);                                   \
    FMA2(_i8,  A1_8,  S##8,  S##7);                                   \
    FMA2(_i9,  A1_9,  S##9,  S##8);                                   \
    FMA2(_i10, A1_10, S##10, S##9);                                   \
    FMA2(D##0,  A2_0,  D##0,  _i0);                                   \
    FMA2(D##1,  A2_1,  D##1,  _i1);                                   \
    FMA2(D##2,  A2_2,  D##2,  _i2);                                   \
    FMA2(D##3,  A2_3,  D##3,  _i3);                                   \
    FMA2(D##4,  A2_4,  D##4,  _i4);                                   \
    FMA2(D##5,  A2_5,  D##5,  _i5);                                   \
    FMA2(D##6,  A2_6,  D##6,  _i6);                                   \
    FMA2(D##7,  A2_7,  D##7,  _i7);                                   \
    FMA2(D##8,  A2_8,  D##8,  _i8);                                   \
    FMA2(D##9,  A2_9,  D##9,  _i9);                                   \
    FMA2(D##10, A2_10, D##10, _i10); }

// Two steps (sa->sb, sb->sa) with dual-row accumulating OLA at OFF, OFF+1.
#define ST2_ACC(OFF, iL0, iH0, iL1, iH1) {                            \
    float _oL0 = obL[(OFF)],   _oH0 = obH[(OFF)],   _w0 = wb[(OFF)];   \
    float _oL1 = obL[(OFF)+1], _oH1 = obH[(OFF)+1], _w1 = wb[(OFF)+1]; \
    u64 _p, _x;                                                        \
    PK2(_p, (iL0), (iH0)); MUL2(_x, G, _p);                            \
    CAS2(sa, sb, _x);                                                  \
    { float _yL, _yH; UP2(_yL, _yH, sb10);                             \
      obL[(OFF)]   = fmaf(_yL, _w0, _oL0);                             \
      obH[(OFF)]   = fmaf(_yH, _w0, _oH0); }                           \
    PK2(_p, (iL1), (iH1)); MUL2(_x, G, _p);                            \
    CAS2(sb, sa, _x);                                                  \
    { float _yL, _yH; UP2(_yL, _yH, sa10);                             \
      obL[(OFF)+1] = fmaf(_yL, _w1, _oL1);                             \
      obH[(OFF)+1] = fmaf(_yH, _w1, _oH1); } }

// Two steps with first-write OLA (chunk 0): pure stores.
#define ST2_ST(OFF, iL0, iH0, iL1, iH1) {                             \
    float _w0 = wb[(OFF)], _w1 = wb[(OFF)+1];                          \
    u64 _p, _x;                                                        \
    PK2(_p, (iL0), (iH0)); MUL2(_x, G, _p);                            \
    CAS2(sa, sb, _x);                                                  \
    { float _yL, _yH; UP2(_yL, _yH, sb10);                             \
      obL[(OFF)]   = _yL * _w0;  obH[(OFF)]   = _yH * _w0; }           \
    PK2(_p, (iL1), (iH1)); MUL2(_x, G, _p);                            \
    CAS2(sb, sa, _x);                                                  \
    { float _yL, _yH; UP2(_yL, _yH, sa10);                             \
      obL[(OFF)+1] = _yL * _w1;  obH[(OFF)+1] = _yH * _w1; } }

// Two pipeline-fill steps (no OLA).
#define PRO2(iL0, iH0, iL1, iH1) {                                    \
    u64 _p, _x;                                                        \
    PK2(_p, (iL0), (iH0)); MUL2(_x, G, _p);                            \
    CAS2(sa, sb, _x);                                                  \
    PK2(_p, (iL1), (iH1)); MUL2(_x, G, _p);                            \
    CAS2(sb, sa, _x); }

// 8-step superstep bodies: carries xL0,xL1/xH0,xH1 (2 samples) + quads
// cL0,cL1 / cH0,cH1 (8 more samples; 6 consumed, 2 become next carries).
#define SS8(ST2)                                                       \
    ST2(0, xL0,   xH0,   xL1,   xH1)                                   \
    ST2(2, cL0.x, cH0.x, cL0.y, cH0.y)                                 \
    ST2(4, cL0.z, cH0.z, cL0.w, cH0.w)                                 \
    ST2(6, cL1.x, cH1.x, cL1.y, cH1.y)

#define ROTATE()                                                       \
    xL0 = cL1.z; xL1 = cL1.w; xH0 = cH1.z; xH1 = cH1.w;                \
    cL0 = nL0; cL1 = nL1; cH0 = nH0; cH1 = nH1;

// Guarded 16B-aligned quad load of input elements t = 4k..4k+3.
__device__ __forceinline__ float4 ld4g(const float* __restrict__ xp, int pos0, int k) {
    int pos = pos0 + 4 * k;
    if ((unsigned)pos <= (unsigned)(NT - 4))
        return *(const float4*)(xp + 4 * k);
    return make_float4(0.f, 0.f, 0.f, 0.f);
}

__global__ __launch_bounds__(NFB) void synth_kernel(const float* __restrict__ ex,
                                                    const float* __restrict__ gain,
                                                    const float* __restrict__ bq,
                                                    float* __restrict__ out) {
    extern __shared__ float sm[];
    float* out_s = sm;                // SMEMN floats
    float* win_s = sm + SMEMN;        // WINL floats

    const int b   = blockIdx.y;
    const int blk = blockIdx.x;
    const int F0  = blk * FPB;
    const int S0  = F0 * HOP;
    const int tid = (int)threadIdx.x;

    // Two frames per lane: fL = F0+tid, fH = fL+32 (disjoint strips).
    const int   pos0L = S0 + tid * HOP - PADW;
    const int   pos0H = pos0L + 32 * HOP;
    const float* xpL  = ex + (size_t)b * NT + pos0L;
    const float* xpH  = ex + (size_t)b * NT + pos0H;

    // Early input loads: prologue quads 0..2, chunk-0 quads 3,4 (both strips)
    float4 qL0 = ld4g(xpL, pos0L, 0), qH0 = ld4g(xpH, pos0H, 0);
    float4 qL1 = ld4g(xpL, pos0L, 1), qH1 = ld4g(xpH, pos0H, 1);
    float4 qL2 = ld4g(xpL, pos0L, 2), qH2 = ld4g(xpH, pos0H, 2);
    float4 cL0 = ld4g(xpL, pos0L, 3), cH0 = ld4g(xpH, pos0H, 3);
    float4 cL1 = ld4g(xpL, pos0L, 4), cH1 = ld4g(xpH, pos0H, 4);

    // ---- Phase A: zero out_s tail rows; window table
    for (int i = FPB * HOP + tid; i < SPAN; i += NFB) out_s[pidx(i)] = 0.f;
    for (int i = tid; i < WINL; i += NFB) win_s[i] = hannw(i);

    // ---- Per-frame-pair gain and coefficients (negated, frame-packed)
    const int fL = F0 + tid;
    u64 G; PK2(G, gain[b * NFRM + fL], gain[b * NFRM + fL + 32]);
    const float* bpL = bq + (size_t)(b * NFRM + fL) * (NSTAGE * 3);
    const float* bpH = bpL + 32 * (NSTAGE * 3);
    u64 A1_0,A1_1,A1_2,A1_3,A1_4,A1_5,A1_6,A1_7,A1_8,A1_9,A1_10;
    u64 A2_0,A2_1,A2_2,A2_3,A2_4,A2_5,A2_6,A2_7,A2_8,A2_9,A2_10;
    PK2(A1_0,  -bpL[1],  -bpH[1]);   PK2(A2_0,  -bpL[2],  -bpH[2]);
    PK2(A1_1,  -bpL[4],  -bpH[4]);   PK2(A2_1,  -bpL[5],  -bpH[5]);
    PK2(A1_2,  -bpL[7],  -bpH[7]);   PK2(A2_2,  -bpL[8],  -bpH[8]);
    PK2(A1_3,  -bpL[10], -bpH[10]);  PK2(A2_3,  -bpL[11], -bpH[11]);
    PK2(A1_4,  -bpL[13], -bpH[13]);  PK2(A2_4,  -bpL[14], -bpH[14]);
    PK2(A1_5,  -bpL[16], -bpH[16]);  PK2(A2_5,  -bpL[17], -bpH[17]);
    PK2(A1_6,  -bpL[19], -bpH[19]);  PK2(A2_6,  -bpL[20], -bpH[20]);
    PK2(A1_7,  -bpL[22], -bpH[22]);  PK2(A2_7,  -bpL[23], -bpH[23]);
    PK2(A1_8,  -bpL[25], -bpH[25]);  PK2(A2_8,  -bpL[26], -bpH[26]);
    PK2(A1_9,  -bpL[28], -bpH[28]);  PK2(A2_9,  -bpL[29], -bpH[29]);
    PK2(A1_10, -bpL[31], -bpH[31]);  PK2(A2_10, -bpL[32], -bpH[32]);

    // Frame-packed ping-pong filter state
    u64 sa0=0,sa1=0,sa2=0,sa3=0,sa4=0,sa5=0,sa6=0,sa7=0,sa8=0,sa9=0,sa10=0;
    u64 sb0=0,sb1=0,sb2=0,sb3=0,sb4=0,sb5=0,sb6=0,sb7=0,sb8=0,sb9=0,sb10=0;

    __syncwarp();   // out_s tail + win_s visible warp-wide

    // ---- Prologue: t = 0..9 fill the filter pipeline (no output)
    PRO2(qL0.x, qH0.x, qL0.y, qH0.y);
    PRO2(qL0.z, qH0.z, qL0.w, qH0.w);
    PRO2(qL1.x, qH1.x, qL1.y, qH1.y);
    PRO2(qL1.z, qH1.z, qL1.w, qH1.w);
    PRO2(qL2.x, qH2.x, qL2.y, qH2.y);
    float xL0 = qL2.z, xL1 = qL2.w;          // carries: t = 10, 11
    float xH0 = qH2.z, xH1 = qH2.w;

    // ---- Chunk 0: t in [10,138), outputs j in [0,128). Pure stores.
    // Superstep ss consumes quads 3+2ss, 4+2ss; prefetches 5+2ss, 6+2ss.
    {
        float* obL = out_s + tid * 129;
        float* obH = out_s + (tid + 32) * 129;
        const float* wb = win_s;
        #pragma unroll 2
        for (int ss = 0; ss < 16; ++ss) {
            const int kq = 5 + 2 * ss;
            float4 nL0 = ld4g(xpL, pos0L, kq),     nH0 = ld4g(xpH, pos0H, kq);
            float4 nL1 = ld4g(xpL, pos0L, kq + 1), nH1 = ld4g(xpH, pos0H, kq + 1);
            SS8(ST2_ST)
            ROTATE()
            obL += 8; obH += 8; wb += 8;
        }
        __syncwarp();
    }

    // ---- Chunks 1,2: accumulating OLA.
    #pragma unroll 1
    for (int c = 1; c <= 2; ++c) {
        float* obL = out_s + tid * 129 + 129 * c;        // 128c + (j>>7) folded
        float* obH = out_s + (tid + 32) * 129 + 129 * c;
        const float* wb = win_s + 128 * c;
        const int kqb = 5 + 32 * c;
        #pragma unroll 2
        for (int ss = 0; ss < 16; ++ss) {
            const int kq = kqb + 2 * ss;
            float4 nL0 = ld4g(xpL, pos0L, kq),     nH0 = ld4g(xpH, pos0H, kq);
            float4 nL1 = ld4g(xpL, pos0L, kq + 1), nH1 = ld4g(xpH, pos0H, kq + 1);
            SS8(ST2_ACC)
            ROTATE()
            obL += 8; obH += 8; wb += 8;
        }
        __syncwarp();
    }

    // ---- Chunk 3: t in [394,522). Uniform ss 0..12; ss13 peeled (prefetch
    // only quad 127); ss14/15 peeled with zero-input pipeline drain (t>=512).
    {
        float* obL = out_s + tid * 129 + 129 * 3;
        float* obH = out_s + (tid + 32) * 129 + 129 * 3;
        const float* wb = win_s + 384;
        #pragma unroll 2
        for (int ss = 0; ss < 13; ++ss) {
            const int kq = 101 + 2 * ss;
            float4 nL0 = ld4g(xpL, pos0L, kq),     nH0 = ld4g(xpH, pos0H, kq);
            float4 nL1 = ld4g(xpL, pos0L, kq + 1), nH1 = ld4g(xpH, pos0H, kq + 1);
            SS8(ST2_ACC)
            ROTATE()
            obL += 8; obH += 8; wb += 8;
        }
        // ss13: t = 498..505; after it, carries = t 506,507; cL0 <- quad 127
        {
            float4 qqL = ld4g(xpL, pos0L, 127), qqH = ld4g(xpH, pos0H, 127);
            SS8(ST2_ACC)
            xL0 = cL1.z; xL1 = cL1.w; xH0 = cH1.z; xH1 = cH1.w;
            cL0 = qqL; cH0 = qqH;
            obL += 8; obH += 8; wb += 8;
        }
        // ss14: t = 506..513 (t>=512 -> zero input)
        ST2_ACC(0, xL0,   xH0,   xL1,   xH1)
        ST2_ACC(2, cL0.x, cH0.x, cL0.y, cH0.y)
        ST2_ACC(4, cL0.z, cH0.z, cL0.w, cH0.w)
        ST2_ACC(6, 0.f, 0.f, 0.f, 0.f)
        obL += 8; obH += 8; wb += 8;
        // ss15: t = 514..521, all-zero drain
        ST2_ACC(0, 0.f, 0.f, 0.f, 0.f)
        ST2_ACC(2, 0.f, 0.f, 0.f, 0.f)
        ST2_ACC(4, 0.f, 0.f, 0.f, 0.f)
        ST2_ACC(6, 0.f, 0.f, 0.f, 0.f)
        __syncwarp();
    }

    // ---- Phase C: write out. Interior norm == 2.0; halos via atomics into
    // pre-zeroed columns.
    const int lo = (F0 == 0) ? 0 : 384;
    const int hi = (F0 + FPB >= NFRM) ? SPAN : FPB * HOP;
    for (int i = tid; i < SPAN; i += NFB) {
        int p = S0 + i;
        int u = p - PADW;
        if (u < 0 || u >= NT) continue;
        float w = out_s[pidx(i)];
        if (p >= 384 && p < NFRM * HOP) w *= 0.5f;
        else                            w /= norm_at(p);
        float* dst = out + (size_t)b * NT + u;
        if (i >= lo && i < hi) *dst = w;
        else                   atomicAdd(dst, w);
    }
}

extern "C" void kernel_launch(void* const* d_in, const int* in_sizes, int n_in,
                              void* d_out, int out_size) {
    const float* ex   = (const float*)d_in[0];   // (32, 131072) f32
    const float* gain = (const float*)d_in[1];   // (32, 1024)   f32
    const float* bq   = (const float*)d_in[2];   // (32, 1024, 11, 3) f32
    float* out = (float*)d_out;                  // (32, 131072) f32

    cudaFuncSetAttribute(synth_kernel, cudaFuncAttributeMaxDynamicSharedMemorySize,
                         (int)SMEM_BYTES);

    halo_zero_kernel<<<dim3(BLK_PER_B - 1, NB), 384>>>(out);
    synth_kernel<<<dim3(BLK_PER_B, NB), NFB, SMEM_BYTES>>>(ex, gain, bq, out);
}

// round 10
// speedup vs baseline: 1.4032x; 1.4032x over previous
#include <cuda_runtime.h>
#include <cstdint>

// Problem constants
#define HOP     128
#define WINL    512
#define PADW    192
#define NB      32
#define NT      131072
#define NFRM    1024
#define NSTAGE  11

// Tiling: one warp per block, one frame per lane (single wave: 1024 warps)
#define NFB     32
#define BLK_PER_B (NFRM / NFB)             // 32
#define SPAN    ((NFB - 1) * HOP + WINL)   // 4480
#define NROWS   (SPAN / HOP)               // 35
#define SMEMN   (NROWS * (HOP + 1))        // 4515 floats (129-word rows)
#define SMEM_BYTES ((SMEMN + WINL) * sizeof(float))   // ~20.1 KB

#define TWO_PI_OVER_WIN 0.012271846303085129f

__device__ __forceinline__ int pidx(int i) { return i + (i >> 7); }

__device__ __forceinline__ float hannw(int n) {
    return 0.5f - 0.5f * __cosf((float)n * TWO_PI_OVER_WIN);
}

__device__ float norm_at(int p) {
    int f_hi = p >> 7; if (f_hi > NFRM - 1) f_hi = NFRM - 1;
    int f_lo = (p >= 384) ? ((p - 384) >> 7) : 0;
    float s = 0.f;
    for (int f = f_lo; f <= f_hi; ++f) s += hannw(p - (f << 7));
    return s;
}

__global__ void halo_zero_kernel(float* __restrict__ out) {
    int b   = blockIdx.y;
    int blk = blockIdx.x + 1;
    int u   = blk * (NFB * HOP) - PADW + (int)threadIdx.x;
    out[(size_t)b * NT + u] = 0.f;
}

// One cascade step: DST[s] = -a1[s]*SRC[s] - a2[s]*DST[s] + in(s),
// in(0)=X (pre-scaled by g), in(s)=SRC[s-1]. 22 independent FMAs.
#define CASCADE(SRC, DST, X)                                          \
    DST##0  = fmaf(na2_0,  DST##0,  fmaf(na1_0,  SRC##0,  (X)));      \
    DST##1  = fmaf(na2_1,  DST##1,  fmaf(na1_1,  SRC##1,  SRC##0));   \
    DST##2  = fmaf(na2_2,  DST##2,  fmaf(na1_2,  SRC##2,  SRC##1));   \
    DST##3  = fmaf(na2_3,  DST##3,  fmaf(na1_3,  SRC##3,  SRC##2));   \
    DST##4  = fmaf(na2_4,  DST##4,  fmaf(na1_4,  SRC##4,  SRC##3));   \
    DST##5  = fmaf(na2_5,  DST##5,  fmaf(na1_5,  SRC##5,  SRC##4));   \
    DST##6  = fmaf(na2_6,  DST##6,  fmaf(na1_6,  SRC##6,  SRC##5));   \
    DST##7  = fmaf(na2_7,  DST##7,  fmaf(na1_7,  SRC##7,  SRC##6));   \
    DST##8  = fmaf(na2_8,  DST##8,  fmaf(na1_8,  SRC##8,  SRC##7));   \
    DST##9  = fmaf(na2_9,  DST##9,  fmaf(na1_9,  SRC##9,  SRC##8));   \
    DST##10 = fmaf(na2_10, DST##10, fmaf(na1_10, SRC##10, SRC##9));

// ---- Prefetch macros (fill the "next" register arrays) ----
// Inputs: 4 quads -> 16 pre-scaled samples; carry cz/cw bridges quad misalign.
#define PF_IN(XN, KQ) {                                               \
    float4 _n0 = ld4g(xp, pos0, (KQ));                                 \
    float4 _n1 = ld4g(xp, pos0, (KQ) + 1);                             \
    float4 _n2 = ld4g(xp, pos0, (KQ) + 2);                             \
    float4 _n3 = ld4g(xp, pos0, (KQ) + 3);                             \
    XN[0]  = g * cz;    XN[1]  = g * cw;                               \
    XN[2]  = g * _n0.x; XN[3]  = g * _n0.y;                            \
    XN[4]  = g * _n0.z; XN[5]  = g * _n0.w;                            \
    XN[6]  = g * _n1.x; XN[7]  = g * _n1.y;                            \
    XN[8]  = g * _n1.z; XN[9]  = g * _n1.w;                            \
    XN[10] = g * _n2.x; XN[11] = g * _n2.y;                            \
    XN[12] = g * _n2.z; XN[13] = g * _n2.w;                            \
    XN[14] = g * _n3.x; XN[15] = g * _n3.y;                            \
    cz = _n3.z; cw = _n3.w; }

// Chunk-3 tail inputs: only quad 127 valid; rest is zero-input drain.
#define PF_IN_TAIL(XN) {                                              \
    float4 _q = ld4g(xp, pos0, 127);                                   \
    XN[0] = g * cz;   XN[1] = g * cw;                                  \
    XN[2] = g * _q.x; XN[3] = g * _q.y;                                \
    XN[4] = g * _q.z; XN[5] = g * _q.w;                                \
    _Pragma("unroll") for (int _k = 6; _k < 16; ++_k) XN[_k] = 0.f; }

#define PF_O(ON, OFF)                                                  \
    _Pragma("unroll") for (int _k = 0; _k < 16; ++_k) ON[_k] = ob[(OFF) + _k];
#define PF_W(WN, OFF)                                                  \
    _Pragma("unroll") for (int _k = 0; _k < 16; ++_k) WN[_k] = wb[(OFF) + _k];

// ---- Superstep bodies: 16 steps, all operands already in registers ----
#define BPAIR_ST(OFF, K, X, W)                                         \
    CASCADE(pa, pb, X[(K)]);     ob[(OFF)+(K)]   = pb10 * W[(K)];      \
    CASCADE(pb, pa, X[(K)+1]);   ob[(OFF)+(K)+1] = pa10 * W[(K)+1];
#define BODY_ST(OFF, X, W)                                             \
    BPAIR_ST(OFF, 0, X, W)  BPAIR_ST(OFF, 2, X, W)                     \
    BPAIR_ST(OFF, 4, X, W)  BPAIR_ST(OFF, 6, X, W)                     \
    BPAIR_ST(OFF, 8, X, W)  BPAIR_ST(OFF, 10, X, W)                    \
    BPAIR_ST(OFF, 12, X, W) BPAIR_ST(OFF, 14, X, W)

#define BPAIR_ACC(OFF, K, X, O, W)                                     \
    CASCADE(pa, pb, X[(K)]);                                           \
    ob[(OFF)+(K)]   = fmaf(pb10, W[(K)],   O[(K)]);                    \
    CASCADE(pb, pa, X[(K)+1]);                                         \
    ob[(OFF)+(K)+1] = fmaf(pa10, W[(K)+1], O[(K)+1]);
#define BODY_ACC(OFF, X, O, W)                                         \
    BPAIR_ACC(OFF, 0, X, O, W)  BPAIR_ACC(OFF, 2, X, O, W)             \
    BPAIR_ACC(OFF, 4, X, O, W)  BPAIR_ACC(OFF, 6, X, O, W)             \
    BPAIR_ACC(OFF, 8, X, O, W)  BPAIR_ACC(OFF, 10, X, O, W)            \
    BPAIR_ACC(OFF, 12, X, O, W) BPAIR_ACC(OFF, 14, X, O, W)

// Guarded 16B-aligned quad load of input elements t = 4k..4k+3.
__device__ __forceinline__ float4 ld4g(const float* __restrict__ xp, int pos0, int k) {
    int pos = pos0 + 4 * k;
    if ((unsigned)pos <= (unsigned)(NT - 4))
        return *(const float4*)(xp + 4 * k);
    return make_float4(0.f, 0.f, 0.f, 0.f);
}

__global__ __launch_bounds__(NFB) void synth_kernel(const float* __restrict__ ex,
                                                    const float* __restrict__ gain,
                                                    const float* __restrict__ bq,
                                                    float* __restrict__ out) {
    extern __shared__ float sm[];
    float* out_s = sm;                // SMEMN floats
    float* win_s = sm + SMEMN;        // WINL floats

    const int b   = blockIdx.y;
    const int blk = blockIdx.x;
    const int F0  = blk * NFB;
    const int S0  = F0 * HOP;
    const int tid = (int)threadIdx.x;
    const int kbase = tid * (HOP + 1);

    // Per-thread input stream (element t=0; may be out of range at edges)
    const int   pos0 = S0 + tid * HOP - PADW;
    const float* xp  = ex + (size_t)b * NT + pos0;

    // Early loads: quads 0..6 (prologue t=0..9 + chunk-0 ss0 inputs t=10..25)
    float4 q0 = ld4g(xp, pos0, 0);
    float4 q1 = ld4g(xp, pos0, 1);
    float4 q2 = ld4g(xp, pos0, 2);
    float4 q3 = ld4g(xp, pos0, 3);
    float4 q4 = ld4g(xp, pos0, 4);
    float4 q5 = ld4g(xp, pos0, 5);
    float4 q6 = ld4g(xp, pos0, 6);

    // ---- Phase A: zero out_s tail rows; window table
    for (int i = NFB * HOP + tid; i < SPAN; i += NFB) out_s[pidx(i)] = 0.f;
    for (int i = tid; i < WINL; i += NFB) win_s[i] = hannw(i);

    // ---- Per-frame coefficients (negated for FMA form)
    const int f = F0 + tid;
    const float g = gain[b * NFRM + f];
    const float* bp = bq + (size_t)(b * NFRM + f) * (NSTAGE * 3);
    const float na1_0  = -bp[1],  na2_0  = -bp[2];
    const float na1_1  = -bp[4],  na2_1  = -bp[5];
    const float na1_2  = -bp[7],  na2_2  = -bp[8];
    const float na1_3  = -bp[10], na2_3  = -bp[11];
    const float na1_4  = -bp[13], na2_4  = -bp[14];
    const float na1_5  = -bp[16], na2_5  = -bp[17];
    const float na1_6  = -bp[19], na2_6  = -bp[20];
    const float na1_7  = -bp[22], na2_7  = -bp[23];
    const float na1_8  = -bp[25], na2_8  = -bp[26];
    const float na1_9  = -bp[28], na2_9  = -bp[29];
    const float na1_10 = -bp[31], na2_10 = -bp[32];

    float pa0 = 0.f, pa1 = 0.f, pa2 = 0.f, pa3 = 0.f, pa4 = 0.f, pa5 = 0.f,
          pa6 = 0.f, pa7 = 0.f, pa8 = 0.f, pa9 = 0.f, pa10 = 0.f;
    float pb0 = 0.f, pb1 = 0.f, pb2 = 0.f, pb3 = 0.f, pb4 = 0.f, pb5 = 0.f,
          pb6 = 0.f, pb7 = 0.f, pb8 = 0.f, pb9 = 0.f, pb10 = 0.f;

    // Double-buffered operand arrays (all indices compile-time -> registers)
    float xA[16], xB[16], oA[16], oB[16], wA[16], wB[16];
    float cz, cw;

    __syncwarp();   // Phase A stores visible warp-wide

    // ---- Prologue: t = 0..9 fill the filter pipeline; build xA (t=10..25)
    CASCADE(pa, pb, g * q0.x); CASCADE(pb, pa, g * q0.y);
    CASCADE(pa, pb, g * q0.z); CASCADE(pb, pa, g * q0.w);
    CASCADE(pa, pb, g * q1.x); CASCADE(pb, pa, g * q1.y);
    CASCADE(pa, pb, g * q1.z); CASCADE(pb, pa, g * q1.w);
    CASCADE(pa, pb, g * q2.x); CASCADE(pb, pa, g * q2.y);
    xA[0]  = g * q2.z; xA[1]  = g * q2.w;
    xA[2]  = g * q3.x; xA[3]  = g * q3.y; xA[4]  = g * q3.z; xA[5]  = g * q3.w;
    xA[6]  = g * q4.x; xA[7]  = g * q4.y; xA[8]  = g * q4.z; xA[9]  = g * q4.w;
    xA[10] = g * q5.x; xA[11] = g * q5.y; xA[12] = g * q5.z; xA[13] = g * q5.w;
    xA[14] = g * q6.x; xA[15] = g * q6.y;
    cz = q6.z; cw = q6.w;

    // ---- Chunk 0: outputs j in [0,128). Pure stores (first writes).
    {
        float* ob = out_s + kbase;
        const float* wb = win_s;
        PF_W(wA, 0);
        #pragma unroll 1
        for (int off = 0; off < 96; off += 32) {
            PF_IN(xB, 7 + (off >> 2));     PF_W(wB, off + 16);
            BODY_ST(off, xA, wA)
            PF_IN(xA, 11 + (off >> 2));    PF_W(wA, off + 32);
            BODY_ST(off + 16, xB, wB)
        }
        PF_IN(xB, 31);  PF_W(wB, 112);
        BODY_ST(96, xA, wA)
        PF_IN(xA, 35);  PF_W(wA, 128);     // next chunk's inputs + window
        BODY_ST(112, xB, wB)
        __syncwarp();
    }

    // ---- Chunks 1,2: accumulating OLA.
    #pragma unroll 1
    for (int c = 1; c <= 2; ++c) {
        float* ob = out_s + kbase + 129 * c;     // 128c + (j>>7) folded in
        const float* wb = win_s + 128 * c;
        const int kq0 = 7 + 32 * c;
        PF_O(oA, 0);                              // after syncwarp: race-free
        #pragma unroll 1
        for (int off = 0; off < 96; off += 32) {
            PF_IN(xB, kq0 + (off >> 2));     PF_O(oB, off + 16); PF_W(wB, off + 16);
            BODY_ACC(off, xA, oA, wA)
            PF_IN(xA, kq0 + 4 + (off >> 2)); PF_O(oA, off + 32); PF_W(wA, off + 32);
            BODY_ACC(off + 16, xB, oB, wB)
        }
        PF_IN(xB, kq0 + 24);  PF_O(oB, 112);  PF_W(wB, 112);
        BODY_ACC(96, xA, oA, wA)
        PF_IN(xA, kq0 + 28);  PF_W(wA, 128);  // NO oo prefetch across the barrier
        BODY_ACC(112, xB, oB, wB)
        __syncwarp();
    }

    // ---- Chunk 3: outputs j in [384,512); inputs end at t=512 (drain).
    {
        float* ob = out_s + kbase + 129 * 3;
        const float* wb = win_s + 384;
        PF_O(oA, 0);
        #pragma unroll 1
        for (int off = 0; off < 96; off += 32) {
            PF_IN(xB, 103 + (off >> 2));  PF_O(oB, off + 16); PF_W(wB, off + 16);
            BODY_ACC(off, xA, oA, wA)
            PF_IN(xA, 107 + (off >> 2));  PF_O(oA, off + 32); PF_W(wA, off + 32);
            BODY_ACC(off + 16, xB, oB, wB)
        }
        PF_IN_TAIL(xB);  PF_O(oB, 112);  PF_W(wB, 112);
        BODY_ACC(96, xA, oA, wA)
        BODY_ACC(112, xB, oB, wB)
        __syncwarp();
    }

    // ---- Phase C: write out. Interior norm == 2.0; halos via atomics into
    // pre-zeroed columns.
    const int lo = (F0 == 0) ? 0 : 384;
    const int hi = (F0 + NFB >= NFRM) ? SPAN : NFB * HOP;
    for (int i = tid; i < SPAN; i += NFB) {
        int p = S0 + i;
        int u = p - PADW;
        if (u < 0 || u >= NT) continue;
        float w = out_s[pidx(i)];
        if (p >= 384 && p < NFRM * HOP) w *= 0.5f;
        else                            w /= norm_at(p);
        float* dst = out + (size_t)b * NT + u;
        if (i >= lo && i < hi) *dst = w;
        else                   atomicAdd(dst, w);
    }
}

extern "C" void kernel_launch(void* const* d_in, const int* in_sizes, int n_in,
                              void* d_out, int out_size) {
    const float* ex   = (const float*)d_in[0];   // (32, 131072) f32
    const float* gain = (const float*)d_in[1];   // (32, 1024)   f32
    const float* bq   = (const float*)d_in[2];   // (32, 1024, 11, 3) f32
    float* out = (float*)d_out;                  // (32, 131072) f32

    cudaFuncSetAttribute(synth_kernel, cudaFuncAttributeMaxDynamicSharedMemorySize,
                         (int)SMEM_BYTES);

    halo_zero_kernel<<<dim3(BLK_PER_B - 1, NB), 384>>>(out);
    synth_kernel<<<dim3(BLK_PER_B, NB), NFB, SMEM_BYTES>>>(ex, gain, bq, out);
}